// round 5
// baseline (speedup 1.0000x reference)
#include <cuda_runtime.h>
#include <cstdint>

typedef unsigned long long u64;
typedef unsigned int u32;

__device__ __forceinline__ u64 ffma2(u64 a, u64 b, u64 c) {
    u64 d; asm("fma.rn.f32x2 %0, %1, %2, %3;" : "=l"(d) : "l"(a), "l"(b), "l"(c)); return d;
}
__device__ __forceinline__ u64 pack2(float x, float y) {
    u64 r; asm("mov.b64 %0, {%1, %2};" : "=l"(r) : "f"(x), "f"(y)); return r;
}
__device__ __forceinline__ float2 unpack2(u64 v) {
    float2 r; asm("mov.b64 {%0, %1}, %2;" : "=f"(r.x), "=f"(r.y) : "l"(v)); return r;
}
__device__ __forceinline__ float clip1(float v) { return fminf(fmaxf(v, -1.0f), 1.0f); }
__device__ __forceinline__ u64 shflx64(u64 v, int m) {
    u32 lo = (u32)v, hi = (u32)(v >> 32);
    lo = __shfl_xor_sync(0xffffffffu, lo, m);
    hi = __shfl_xor_sync(0xffffffffu, hi, m);
    return ((u64)hi << 32) | (u64)lo;
}
__device__ __forceinline__ u64 shfl64(u64 v, int src) {
    u32 lo = (u32)v, hi = (u32)(v >> 32);
    lo = __shfl_sync(0xffffffffu, lo, src);
    hi = __shfl_sync(0xffffffffu, hi, src);
    return ((u64)hi << 32) | (u64)lo;
}

constexpr int NTHREADS = 256;
constexpr int NGROUP   = 4;          // 2 warps per group
constexpr int ROWS_G   = 16;         // rows per group
constexpr int ROWS_B   = NGROUP * ROWS_G;   // 64 rows per block-iteration
constexpr int INSTRIDE = 386;        // 386 mod 32 = 2 -> conflict-free across 16 rows
constexpr int VSTRIDE  = 38;

constexpr int SW1_N = 27 * 8;
constexpr int SW2_N = 4 * 8;
constexpr int E1T_N = 19 * 16;
constexpr int E2T_N = 8 * 16;
constexpr int E3S_N = 8;
constexpr int WU_N  = SW1_N + SW2_N + E1T_N + E2T_N + E3S_N;
constexpr int IN_N  = NGROUP * ROWS_G * INSTRIDE;   // floats
constexpr int VB_N  = NGROUP * ROWS_G * VSTRIDE;    // floats
constexpr size_t SMEM_BYTES = (size_t)WU_N * 8 + (size_t)(IN_N + VB_N + 32) * 4;

__global__ __launch_bounds__(NTHREADS, 2)
void lila_kernel(const float* __restrict__ inp,
                 const float* __restrict__ W1, const float* __restrict__ b1,
                 const float* __restrict__ W2, const float* __restrict__ b2,
                 const float* __restrict__ W3, const float* __restrict__ b3,
                 const float* __restrict__ E1, const float* __restrict__ c1,
                 const float* __restrict__ E2, const float* __restrict__ c2,
                 const float* __restrict__ E3, const float* __restrict__ c3,
                 float* __restrict__ out, int B)
{
    extern __shared__ __align__(16) char smem_raw[];
    u64*   SW1 = reinterpret_cast<u64*>(smem_raw);
    u64*   SW2 = SW1 + SW1_N;
    u64*   E1T = SW2 + SW2_N;
    u64*   E2T = E1T + E1T_N;
    u64*   E3S = E2T + E2T_N;
    float* IN  = reinterpret_cast<float*>(E3S + E3S_N);
    float* VB  = IN + IN_N;
    float* c1S = VB + VB_N;       // 16
    float* c2S = c1S + 16;        // 16

    const int tid  = threadIdx.x;
    const int lane = tid & 31;
    const int warp = tid >> 5;
    const int g    = warp >> 1;   // group 0..3
    const int ws   = warp & 1;    // warp-sub within group
    const int r    = lane >> 1;   // row within group (0..15)
    const int h    = lane & 1;    // output half

    // ---- stage weights / head constants ----
    for (int i = tid; i < SW1_N; i += NTHREADS) {
        int fp = i >> 3, o = i & 7;
        SW1[i] = pack2(W1[(2 * fp) * 8 + o], W1[(2 * fp + 1) * 8 + o]);
    }
    for (int i = tid; i < SW2_N; i += NTHREADS) {
        int fp = i >> 3, o = i & 7;
        SW2[i] = pack2(W2[(2 * fp) * 8 + o], W2[(2 * fp + 1) * 8 + o]);
    }
    for (int i = tid; i < E1T_N; i += NTHREADS) {
        int fp = i >> 4, o = i & 15;
        E1T[i] = (fp < 18) ? pack2(E1[(2 * fp) * 16 + o], E1[(2 * fp + 1) * 16 + o])
                           : pack2(E1[36 * 16 + o], 0.0f);
    }
    for (int i = tid; i < E2T_N; i += NTHREADS) {
        int fp = i >> 4, o = i & 15;
        E2T[i] = pack2(E2[(2 * fp) * 16 + o], E2[(2 * fp + 1) * 16 + o]);
    }
    if (tid < 8)  E3S[tid] = pack2(E3[2 * tid], E3[2 * tid + 1]);
    if (tid < 16) { c1S[tid] = c1[tid]; c2S[tid] = c2[tid]; }

    // ---- per-lane register constants (patch network only) ----
    float b1f[4], b2f[4];
#pragma unroll
    for (int k = 0; k < 4; k++) {
        b1f[k] = __ldg(b1 + 4 * h + k);
        b2f[k] = __ldg(b2 + 4 * h + k);
    }
    const u64 w3p0 = pack2(__ldg(W3 + 4 * h + 0), __ldg(W3 + 4 * h + 1));
    const u64 w3p1 = pack2(__ldg(W3 + 4 * h + 2), __ldg(W3 + 4 * h + 3));
    const float b3s = __ldg(b3);
    const float c3s = __ldg(c3);

    const ulonglong2* SW1v = reinterpret_cast<const ulonglong2*>(SW1);
    const ulonglong2* SW2v = reinterpret_cast<const ulonglong2*>(SW2);
    const ulonglong2* E1Tv = reinterpret_cast<const ulonglong2*>(E1T);
    const ulonglong2* E2Tv = reinterpret_cast<const ulonglong2*>(E2T);

    float* grp_in = IN + g * (ROWS_G * INSTRIDE);
    float* grp_vb = VB + g * (ROWS_G * VSTRIDE);
    float* lane_in = grp_in + r * INSTRIDE;
    float* lane_vb = grp_vb + r * VSTRIDE;

    // head mapping: this warp handles 8 rows
    const int hr  = lane & 7;      // row (within warp's 8)
    const int hoq = lane >> 3;     // output quad
    const float* vrow = grp_vb + (ws * 8 + hr) * VSTRIDE;

    const int rowsPerIter = gridDim.x * ROWS_B;

    for (int rb0 = blockIdx.x * ROWS_B; rb0 < B; rb0 += rowsPerIter) {
        const int rbg = rb0 + g * ROWS_G;        // group's first row
        __syncthreads();

        // ---- stage: this warp stages 8 rows ----
#pragma unroll 1
        for (int rr = 0; rr < 8; rr++) {
            const int rloc = ws * 8 + rr;
            const int row  = rbg + rloc;
            float* dst = grp_in + rloc * INSTRIDE;
            if (row < B) {
                const float* src = inp + (size_t)row * 385;
#pragma unroll
                for (int k = 0; k < 12; k++)
                    dst[lane + 32 * k] = __ldg(src + lane + 32 * k);
                if (lane == 0) {
                    grp_vb[rloc * VSTRIDE + 36] = __ldg(src + 384);
                    grp_vb[rloc * VSTRIDE + 37] = 0.0f;
                }
            } else {
#pragma unroll
                for (int k = 0; k < 12; k++)
                    dst[lane + 32 * k] = 0.0f;
                if (lane == 0) {
                    grp_vb[rloc * VSTRIDE + 36] = 0.0f;
                    grp_vb[rloc * VSTRIDE + 37] = 0.0f;
                }
            }
        }
        __syncthreads();

        // ---- compute: this warp owns x-rows {3*ws, 3*ws+1, 3*ws+2} ----
#pragma unroll 1
        for (int xi = 0; xi < 3; xi++) {
            const int x = 3 * ws + xi;
            const float* base = lane_in + x * 48;

            u64 acc[6][4];
#pragma unroll
            for (int j = 0; j < 6; j++)
#pragma unroll
                for (int q = 0; q < 4; q++) acc[j][q] = 0ull;

            // layer 1: 27 feature-pairs x 6 patches (y = j)
#pragma unroll
            for (int c = 0; c < 9; c++) {
                const int off = (c / 3) * 48 + (c % 3) * 6;
#pragma unroll
                for (int j3 = 0; j3 < 3; j3++) {
                    const int fp = 3 * c + j3;
                    const int coff = off + 2 * j3;
                    const ulonglong2 wa = SW1v[fp * 4 + 2 * h];
                    const ulonglong2 wb = SW1v[fp * 4 + 2 * h + 1];
#pragma unroll
                    for (int j = 0; j < 6; j++) {
                        const u64 iv = *reinterpret_cast<const u64*>(base + j * 6 + coff);
                        acc[j][0] = ffma2(iv, wa.x, acc[j][0]);
                        acc[j][1] = ffma2(iv, wa.y, acc[j][1]);
                        acc[j][2] = ffma2(iv, wb.x, acc[j][2]);
                        acc[j][3] = ffma2(iv, wb.y, acc[j][3]);
                    }
                }
            }

            // epilogue + L2 + L3 per patch
#pragma unroll
            for (int j = 0; j < 6; j++) {
                float2 f0 = unpack2(acc[j][0]);
                float2 f1 = unpack2(acc[j][1]);
                float2 f2 = unpack2(acc[j][2]);
                float2 f3 = unpack2(acc[j][3]);
                u64 m0 = pack2(clip1(f0.x + f0.y + b1f[0]), clip1(f1.x + f1.y + b1f[1]));
                u64 m1 = pack2(clip1(f2.x + f2.y + b1f[2]), clip1(f3.x + f3.y + b1f[3]));
                u64 p0 = shflx64(m0, 1);
                u64 p1 = shflx64(m1, 1);
                u64 x0 = h ? p0 : m0, x1 = h ? p1 : m1;
                u64 x2 = h ? m0 : p0, x3 = h ? m1 : p1;

                u64 a0 = 0ull, a1 = 0ull, a2 = 0ull, a3 = 0ull;
#pragma unroll
                for (int fp = 0; fp < 4; fp++) {
                    const u64 xv = (fp == 0) ? x0 : (fp == 1) ? x1 : (fp == 2) ? x2 : x3;
                    const ulonglong2 wa2 = SW2v[fp * 4 + 2 * h];
                    const ulonglong2 wb2 = SW2v[fp * 4 + 2 * h + 1];
                    a0 = ffma2(xv, wa2.x, a0);
                    a1 = ffma2(xv, wa2.y, a1);
                    a2 = ffma2(xv, wb2.x, a2);
                    a3 = ffma2(xv, wb2.y, a3);
                }
                float2 g0 = unpack2(a0), g1 = unpack2(a1);
                float2 g2 = unpack2(a2), g3 = unpack2(a3);
                u64 n0 = pack2(clip1(g0.x + g0.y + b2f[0]), clip1(g1.x + g1.y + b2f[1]));
                u64 n1 = pack2(clip1(g2.x + g2.y + b2f[2]), clip1(g3.x + g3.y + b2f[3]));

                u64 s = ffma2(n0, w3p0, ffma2(n1, w3p1, 0ull));
                float2 sf = unpack2(s);
                float part = sf.x + sf.y;
                float tot = part + __shfl_xor_sync(0xffffffffu, part, 1);
                if (h == 0) lane_vb[x * 6 + j] = clip1(tot + b3s);
            }
        }
        __syncthreads();

        // ---- head: this warp handles rows rbg + ws*8 + (0..7) ----
        u64 gacc[4] = {0ull, 0ull, 0ull, 0ull};
#pragma unroll
        for (int fp = 0; fp < 19; fp++) {
            const u64 iv = *reinterpret_cast<const u64*>(vrow + 2 * fp);
            const ulonglong2 wa = E1Tv[fp * 8 + 2 * hoq];
            const ulonglong2 wb = E1Tv[fp * 8 + 2 * hoq + 1];
            gacc[0] = ffma2(iv, wa.x, gacc[0]);
            gacc[1] = ffma2(iv, wa.y, gacc[1]);
            gacc[2] = ffma2(iv, wb.x, gacc[2]);
            gacc[3] = ffma2(iv, wb.y, gacc[3]);
        }
        float gv[4];
#pragma unroll
        for (int k = 0; k < 4; k++) {
            float2 f = unpack2(gacc[k]);
            gv[k] = clip1(f.x + f.y + c1S[4 * hoq + k]);
        }
        u64 q0 = pack2(gv[0], gv[1]), q1 = pack2(gv[2], gv[3]);

        u64 z[8];
#pragma unroll
        for (int c = 0; c < 4; c++) {
            z[2 * c]     = shfl64(q0, c * 8 + hr);
            z[2 * c + 1] = shfl64(q1, c * 8 + hr);
        }

        u64 d[4] = {0ull, 0ull, 0ull, 0ull};
#pragma unroll
        for (int fp = 0; fp < 8; fp++) {
            const ulonglong2 wa = E2Tv[fp * 8 + 2 * hoq];
            const ulonglong2 wb = E2Tv[fp * 8 + 2 * hoq + 1];
            d[0] = ffma2(z[fp], wa.x, d[0]);
            d[1] = ffma2(z[fp], wa.y, d[1]);
            d[2] = ffma2(z[fp], wb.x, d[2]);
            d[3] = ffma2(z[fp], wb.y, d[3]);
        }
        float dv[4];
#pragma unroll
        for (int k = 0; k < 4; k++) {
            float2 f = unpack2(d[k]);
            dv[k] = clip1(f.x + f.y + c2S[4 * hoq + k]);
        }
        u64 s = ffma2(pack2(dv[0], dv[1]), E3S[2 * hoq],
                ffma2(pack2(dv[2], dv[3]), E3S[2 * hoq + 1], 0ull));
        float2 sf = unpack2(s);
        float part = sf.x + sf.y;
        part += __shfl_xor_sync(0xffffffffu, part, 8);
        part += __shfl_xor_sync(0xffffffffu, part, 16);
        const int row = rbg + ws * 8 + hr;
        if (hoq == 0 && row < B) out[row] = clip1(part + c3s);
    }
}

extern "C" void kernel_launch(void* const* d_in, const int* in_sizes, int n_in,
                              void* d_out, int out_size)
{
    const float* inp = (const float*)d_in[0];
    const float* W1  = (const float*)d_in[1];
    const float* b1  = (const float*)d_in[2];
    const float* W2  = (const float*)d_in[3];
    const float* b2  = (const float*)d_in[4];
    const float* W3  = (const float*)d_in[5];
    const float* b3  = (const float*)d_in[6];
    const float* E1  = (const float*)d_in[7];
    const float* c1  = (const float*)d_in[8];
    const float* E2  = (const float*)d_in[9];
    const float* c2  = (const float*)d_in[10];
    const float* E3  = (const float*)d_in[11];
    const float* c3  = (const float*)d_in[12];

    int B = in_sizes[0] / 385;

    cudaFuncSetAttribute(lila_kernel, cudaFuncAttributeMaxDynamicSharedMemorySize,
                         (int)SMEM_BYTES);

    lila_kernel<<<296, NTHREADS, SMEM_BYTES>>>(inp, W1, b1, W2, b2, W3, b3,
                                               E1, c1, E2, c2, E3, c3,
                                               (float*)d_out, B);
}

// round 6
// speedup vs baseline: 2.5229x; 2.5229x over previous
#include <cuda_runtime.h>
#include <cstdint>

typedef unsigned long long u64;
typedef unsigned int u32;

__device__ __forceinline__ u64 ffma2(u64 a, u64 b, u64 c) {
    u64 d; asm("fma.rn.f32x2 %0, %1, %2, %3;" : "=l"(d) : "l"(a), "l"(b), "l"(c)); return d;
}
__device__ __forceinline__ u64 pack2(float x, float y) {
    u64 r; asm("mov.b64 %0, {%1, %2};" : "=l"(r) : "f"(x), "f"(y)); return r;
}
__device__ __forceinline__ float2 unpack2(u64 v) {
    float2 r; asm("mov.b64 {%0, %1}, %2;" : "=f"(r.x), "=f"(r.y) : "l"(v)); return r;
}
__device__ __forceinline__ float clip1(float v) { return fminf(fmaxf(v, -1.0f), 1.0f); }
__device__ __forceinline__ u64 shflx64(u64 v, int m) {
    u32 lo = (u32)v, hi = (u32)(v >> 32);
    lo = __shfl_xor_sync(0xffffffffu, lo, m);
    hi = __shfl_xor_sync(0xffffffffu, hi, m);
    return ((u64)hi << 32) | (u64)lo;
}
__device__ __forceinline__ u64 shfl64(u64 v, int src) {
    u32 lo = (u32)v, hi = (u32)(v >> 32);
    lo = __shfl_sync(0xffffffffu, lo, src);
    hi = __shfl_sync(0xffffffffu, hi, src);
    return ((u64)hi << 32) | (u64)lo;
}

constexpr int NTHREADS = 256;
constexpr int NGROUP   = 4;          // 2 warps per group
constexpr int ROWS_G   = 16;         // rows per group
constexpr int ROWS_B   = NGROUP * ROWS_G;   // 64 rows per block-iteration
constexpr int INSTRIDE = 386;        // 386 mod 32 = 2 -> conflict-free across 16 rows
constexpr int VSTRIDE  = 38;

constexpr int SW1_N = 27 * 8;
constexpr int SW2_N = 4 * 8;
constexpr int E1T_N = 19 * 16;
constexpr int E2T_N = 8 * 16;
constexpr int E3S_N = 8;
constexpr int W3S_N = 4;
constexpr int WU_N  = SW1_N + SW2_N + E1T_N + E2T_N + E3S_N + W3S_N;
constexpr int IN_N  = NGROUP * ROWS_G * INSTRIDE;   // floats
constexpr int VB_N  = NGROUP * ROWS_G * VSTRIDE;    // floats
constexpr size_t SMEM_BYTES = (size_t)WU_N * 8 + (size_t)(IN_N + VB_N + 64) * 4;

__global__ __launch_bounds__(NTHREADS, 2)
void lila_kernel(const float* __restrict__ inp,
                 const float* __restrict__ W1, const float* __restrict__ b1,
                 const float* __restrict__ W2, const float* __restrict__ b2,
                 const float* __restrict__ W3, const float* __restrict__ b3,
                 const float* __restrict__ E1, const float* __restrict__ c1,
                 const float* __restrict__ E2, const float* __restrict__ c2,
                 const float* __restrict__ E3, const float* __restrict__ c3,
                 float* __restrict__ out, int B)
{
    extern __shared__ __align__(16) char smem_raw[];
    u64*   SW1 = reinterpret_cast<u64*>(smem_raw);
    u64*   SW2 = SW1 + SW1_N;
    u64*   E1T = SW2 + SW2_N;
    u64*   E2T = E1T + E1T_N;
    u64*   E3S = E2T + E2T_N;
    u64*   W3S = E3S + E3S_N;
    float* IN  = reinterpret_cast<float*>(W3S + W3S_N);
    float* VB  = IN + IN_N;
    float* c1S = VB + VB_N;       // 16
    float* c2S = c1S + 16;        // 16
    float* B1S = c2S + 16;        // 8
    float* B2S = B1S + 8;         // 8

    const int tid  = threadIdx.x;
    const int lane = tid & 31;
    const int warp = tid >> 5;
    const int g    = warp >> 1;   // group 0..3
    const int ws   = warp & 1;    // warp-sub within group
    const int r    = lane >> 1;   // row within group (0..15)
    const int h    = lane & 1;    // output half

    // ---- stage weights / constants ----
    for (int i = tid; i < SW1_N; i += NTHREADS) {
        int fp = i >> 3, o = i & 7;
        SW1[i] = pack2(W1[(2 * fp) * 8 + o], W1[(2 * fp + 1) * 8 + o]);
    }
    for (int i = tid; i < SW2_N; i += NTHREADS) {
        int fp = i >> 3, o = i & 7;
        SW2[i] = pack2(W2[(2 * fp) * 8 + o], W2[(2 * fp + 1) * 8 + o]);
    }
    for (int i = tid; i < E1T_N; i += NTHREADS) {
        int fp = i >> 4, o = i & 15;
        E1T[i] = (fp < 18) ? pack2(E1[(2 * fp) * 16 + o], E1[(2 * fp + 1) * 16 + o])
                           : pack2(E1[36 * 16 + o], 0.0f);
    }
    for (int i = tid; i < E2T_N; i += NTHREADS) {
        int fp = i >> 4, o = i & 15;
        E2T[i] = pack2(E2[(2 * fp) * 16 + o], E2[(2 * fp + 1) * 16 + o]);
    }
    if (tid < 8)  E3S[tid] = pack2(E3[2 * tid], E3[2 * tid + 1]);
    if (tid < 4)  W3S[tid] = pack2(W3[2 * tid], W3[2 * tid + 1]);
    if (tid < 16) { c1S[tid] = c1[tid]; c2S[tid] = c2[tid]; }
    if (tid < 8)  { B1S[tid] = b1[tid]; B2S[tid] = b2[tid]; }

    const float b3s = __ldg(b3);
    const float c3s = __ldg(c3);

    const ulonglong2* SW1v = reinterpret_cast<const ulonglong2*>(SW1);
    const ulonglong2* SW2v = reinterpret_cast<const ulonglong2*>(SW2);
    const ulonglong2* E1Tv = reinterpret_cast<const ulonglong2*>(E1T);
    const ulonglong2* E2Tv = reinterpret_cast<const ulonglong2*>(E2T);

    float* grp_in = IN + g * (ROWS_G * INSTRIDE);
    float* grp_vb = VB + g * (ROWS_G * VSTRIDE);
    float* lane_in = grp_in + r * INSTRIDE;
    float* lane_vb = grp_vb + r * VSTRIDE;

    // head mapping: this warp handles 8 rows
    const int hr  = lane & 7;      // row (within warp's 8)
    const int hoq = lane >> 3;     // output quad
    const float* vrow = grp_vb + (ws * 8 + hr) * VSTRIDE;

    const int rowsPerIter = gridDim.x * ROWS_B;

    __syncthreads();

    for (int rb0 = blockIdx.x * ROWS_B; rb0 < B; rb0 += rowsPerIter) {
        const int rbg = rb0 + g * ROWS_G;        // group's first row
        __syncthreads();

        // ---- stage: this warp stages 8 rows ----
#pragma unroll 1
        for (int rr = 0; rr < 8; rr++) {
            const int rloc = ws * 8 + rr;
            const int row  = rbg + rloc;
            float* dst = grp_in + rloc * INSTRIDE;
            if (row < B) {
                const float* src = inp + (size_t)row * 385;
#pragma unroll
                for (int k = 0; k < 12; k++)
                    dst[lane + 32 * k] = __ldg(src + lane + 32 * k);
                if (lane == 0) {
                    grp_vb[rloc * VSTRIDE + 36] = __ldg(src + 384);
                    grp_vb[rloc * VSTRIDE + 37] = 0.0f;
                }
            } else {
#pragma unroll
                for (int k = 0; k < 12; k++)
                    dst[lane + 32 * k] = 0.0f;
                if (lane == 0) {
                    grp_vb[rloc * VSTRIDE + 36] = 0.0f;
                    grp_vb[rloc * VSTRIDE + 37] = 0.0f;
                }
            }
        }
        __syncthreads();

        // ---- compute: this warp owns x-rows {3*ws, 3*ws+1, 3*ws+2} ----
#pragma unroll 1
        for (int xi = 0; xi < 3; xi++) {
            const int x = 3 * ws + xi;
            const float* base = lane_in + x * 48;

            u64 acc[6][4];
#pragma unroll
            for (int j = 0; j < 6; j++)
#pragma unroll
                for (int q = 0; q < 4; q++) acc[j][q] = 0ull;

            // layer 1: 27 feature-pairs x 6 patches; ox loop NOT unrolled
            // (bounds register pressure -> no spills at 128-reg cap)
#pragma unroll 1
            for (int ox = 0; ox < 3; ox++) {
                const float* brow = base + ox * 48;
#pragma unroll
                for (int oy = 0; oy < 3; oy++) {
#pragma unroll
                    for (int j3 = 0; j3 < 3; j3++) {
                        const int fp = 3 * (3 * ox + oy) + j3;
                        const int coff = oy * 6 + 2 * j3;
                        const ulonglong2 wa = SW1v[fp * 4 + 2 * h];
                        const ulonglong2 wb = SW1v[fp * 4 + 2 * h + 1];
#pragma unroll
                        for (int j = 0; j < 6; j++) {
                            const u64 iv = *reinterpret_cast<const u64*>(brow + j * 6 + coff);
                            acc[j][0] = ffma2(iv, wa.x, acc[j][0]);
                            acc[j][1] = ffma2(iv, wa.y, acc[j][1]);
                            acc[j][2] = ffma2(iv, wb.x, acc[j][2]);
                            acc[j][3] = ffma2(iv, wb.y, acc[j][3]);
                        }
                    }
                }
            }

            // epilogue + L2 + L3 per patch (biases/W3 from SMEM broadcast)
            const float b10 = B1S[4 * h], b11 = B1S[4 * h + 1];
            const float b12 = B1S[4 * h + 2], b13 = B1S[4 * h + 3];
            const float b20 = B2S[4 * h], b21 = B2S[4 * h + 1];
            const float b22 = B2S[4 * h + 2], b23 = B2S[4 * h + 3];
            const u64 w3p0 = W3S[2 * h], w3p1 = W3S[2 * h + 1];

#pragma unroll
            for (int j = 0; j < 6; j++) {
                float2 f0 = unpack2(acc[j][0]);
                float2 f1 = unpack2(acc[j][1]);
                float2 f2 = unpack2(acc[j][2]);
                float2 f3 = unpack2(acc[j][3]);
                u64 m0 = pack2(clip1(f0.x + f0.y + b10), clip1(f1.x + f1.y + b11));
                u64 m1 = pack2(clip1(f2.x + f2.y + b12), clip1(f3.x + f3.y + b13));
                u64 p0 = shflx64(m0, 1);
                u64 p1 = shflx64(m1, 1);
                u64 x0 = h ? p0 : m0, x1 = h ? p1 : m1;
                u64 x2 = h ? m0 : p0, x3 = h ? m1 : p1;

                u64 a0 = 0ull, a1 = 0ull, a2 = 0ull, a3 = 0ull;
#pragma unroll
                for (int fp = 0; fp < 4; fp++) {
                    const u64 xv = (fp == 0) ? x0 : (fp == 1) ? x1 : (fp == 2) ? x2 : x3;
                    const ulonglong2 wa2 = SW2v[fp * 4 + 2 * h];
                    const ulonglong2 wb2 = SW2v[fp * 4 + 2 * h + 1];
                    a0 = ffma2(xv, wa2.x, a0);
                    a1 = ffma2(xv, wa2.y, a1);
                    a2 = ffma2(xv, wb2.x, a2);
                    a3 = ffma2(xv, wb2.y, a3);
                }
                float2 g0 = unpack2(a0), g1 = unpack2(a1);
                float2 g2 = unpack2(a2), g3 = unpack2(a3);
                u64 n0 = pack2(clip1(g0.x + g0.y + b20), clip1(g1.x + g1.y + b21));
                u64 n1 = pack2(clip1(g2.x + g2.y + b22), clip1(g3.x + g3.y + b23));

                u64 s = ffma2(n0, w3p0, ffma2(n1, w3p1, 0ull));
                float2 sf = unpack2(s);
                float part = sf.x + sf.y;
                float tot = part + __shfl_xor_sync(0xffffffffu, part, 1);
                if (h == 0) lane_vb[x * 6 + j] = clip1(tot + b3s);
            }
        }
        __syncthreads();

        // ---- head: this warp handles rows rbg + ws*8 + (0..7) ----
        u64 gacc[4] = {0ull, 0ull, 0ull, 0ull};
#pragma unroll
        for (int fp = 0; fp < 19; fp++) {
            const u64 iv = *reinterpret_cast<const u64*>(vrow + 2 * fp);
            const ulonglong2 wa = E1Tv[fp * 8 + 2 * hoq];
            const ulonglong2 wb = E1Tv[fp * 8 + 2 * hoq + 1];
            gacc[0] = ffma2(iv, wa.x, gacc[0]);
            gacc[1] = ffma2(iv, wa.y, gacc[1]);
            gacc[2] = ffma2(iv, wb.x, gacc[2]);
            gacc[3] = ffma2(iv, wb.y, gacc[3]);
        }
        float gv[4];
#pragma unroll
        for (int k = 0; k < 4; k++) {
            float2 f = unpack2(gacc[k]);
            gv[k] = clip1(f.x + f.y + c1S[4 * hoq + k]);
        }
        u64 q0 = pack2(gv[0], gv[1]), q1 = pack2(gv[2], gv[3]);

        u64 z[8];
#pragma unroll
        for (int c = 0; c < 4; c++) {
            z[2 * c]     = shfl64(q0, c * 8 + hr);
            z[2 * c + 1] = shfl64(q1, c * 8 + hr);
        }

        u64 d[4] = {0ull, 0ull, 0ull, 0ull};
#pragma unroll
        for (int fp = 0; fp < 8; fp++) {
            const ulonglong2 wa = E2Tv[fp * 8 + 2 * hoq];
            const ulonglong2 wb = E2Tv[fp * 8 + 2 * hoq + 1];
            d[0] = ffma2(z[fp], wa.x, d[0]);
            d[1] = ffma2(z[fp], wa.y, d[1]);
            d[2] = ffma2(z[fp], wb.x, d[2]);
            d[3] = ffma2(z[fp], wb.y, d[3]);
        }
        float dv[4];
#pragma unroll
        for (int k = 0; k < 4; k++) {
            float2 f = unpack2(d[k]);
            dv[k] = clip1(f.x + f.y + c2S[4 * hoq + k]);
        }
        u64 s = ffma2(pack2(dv[0], dv[1]), E3S[2 * hoq],
                ffma2(pack2(dv[2], dv[3]), E3S[2 * hoq + 1], 0ull));
        float2 sf = unpack2(s);
        float part = sf.x + sf.y;
        part += __shfl_xor_sync(0xffffffffu, part, 8);
        part += __shfl_xor_sync(0xffffffffu, part, 16);
        const int row = rbg + ws * 8 + hr;
        if (hoq == 0 && row < B) out[row] = clip1(part + c3s);
    }
}

extern "C" void kernel_launch(void* const* d_in, const int* in_sizes, int n_in,
                              void* d_out, int out_size)
{
    const float* inp = (const float*)d_in[0];
    const float* W1  = (const float*)d_in[1];
    const float* b1  = (const float*)d_in[2];
    const float* W2  = (const float*)d_in[3];
    const float* b2  = (const float*)d_in[4];
    const float* W3  = (const float*)d_in[5];
    const float* b3  = (const float*)d_in[6];
    const float* E1  = (const float*)d_in[7];
    const float* c1  = (const float*)d_in[8];
    const float* E2  = (const float*)d_in[9];
    const float* c2  = (const float*)d_in[10];
    const float* E3  = (const float*)d_in[11];
    const float* c3  = (const float*)d_in[12];

    int B = in_sizes[0] / 385;

    cudaFuncSetAttribute(lila_kernel, cudaFuncAttributeMaxDynamicSharedMemorySize,
                         (int)SMEM_BYTES);

    lila_kernel<<<296, NTHREADS, SMEM_BYTES>>>(inp, W1, b1, W2, b2, W3, b3,
                                               E1, c1, E2, c2, E3, c3,
                                               (float*)d_out, B);
}

// round 7
// speedup vs baseline: 2.6610x; 1.0548x over previous
#include <cuda_runtime.h>
#include <cstdint>

typedef unsigned long long u64;
typedef unsigned int u32;

__device__ __forceinline__ u64 ffma2(u64 a, u64 b, u64 c) {
    u64 d; asm("fma.rn.f32x2 %0, %1, %2, %3;" : "=l"(d) : "l"(a), "l"(b), "l"(c)); return d;
}
__device__ __forceinline__ u64 pack2(float x, float y) {
    u64 r; asm("mov.b64 %0, {%1, %2};" : "=l"(r) : "f"(x), "f"(y)); return r;
}
__device__ __forceinline__ float2 unpack2(u64 v) {
    float2 r; asm("mov.b64 {%0, %1}, %2;" : "=f"(r.x), "=f"(r.y) : "l"(v)); return r;
}
__device__ __forceinline__ float clip1(float v) { return fminf(fmaxf(v, -1.0f), 1.0f); }
__device__ __forceinline__ u64 shflx64(u64 v, int m) {
    u32 lo = (u32)v, hi = (u32)(v >> 32);
    lo = __shfl_xor_sync(0xffffffffu, lo, m);
    hi = __shfl_xor_sync(0xffffffffu, hi, m);
    return ((u64)hi << 32) | (u64)lo;
}
__device__ __forceinline__ u64 shfl64(u64 v, int src) {
    u32 lo = (u32)v, hi = (u32)(v >> 32);
    lo = __shfl_sync(0xffffffffu, lo, src);
    hi = __shfl_sync(0xffffffffu, hi, src);
    return ((u64)hi << 32) | (u64)lo;
}
// named barrier: 64 threads (one group = 2 warps)
__device__ __forceinline__ void group_bar(int id) {
    asm volatile("bar.sync %0, 64;" :: "r"(id) : "memory");
}

constexpr int NTHREADS = 256;
constexpr int NGROUP   = 4;          // 2 warps per group
constexpr int ROWS_G   = 16;         // rows per group
constexpr int ROWS_B   = NGROUP * ROWS_G;   // 64 rows per block-iteration
constexpr int INSTRIDE = 386;        // 386 mod 32 = 2 -> conflict-free across 16 rows
constexpr int VSTRIDE  = 38;

constexpr int SW1_N = 27 * 8;
constexpr int SW2_N = 4 * 8;
constexpr int E1T_N = 19 * 16;
constexpr int E2T_N = 8 * 16;
constexpr int E3S_N = 8;
constexpr int W3S_N = 4;
constexpr int WU_N  = SW1_N + SW2_N + E1T_N + E2T_N + E3S_N + W3S_N;
constexpr int IN_N  = NGROUP * ROWS_G * INSTRIDE;   // floats
constexpr int VB_N  = NGROUP * ROWS_G * VSTRIDE;    // floats
constexpr size_t SMEM_BYTES = (size_t)WU_N * 8 + (size_t)(IN_N + VB_N + 64) * 4;

__global__ __launch_bounds__(NTHREADS, 2)
void lila_kernel(const float* __restrict__ inp,
                 const float* __restrict__ W1, const float* __restrict__ b1,
                 const float* __restrict__ W2, const float* __restrict__ b2,
                 const float* __restrict__ W3, const float* __restrict__ b3,
                 const float* __restrict__ E1, const float* __restrict__ c1,
                 const float* __restrict__ E2, const float* __restrict__ c2,
                 const float* __restrict__ E3, const float* __restrict__ c3,
                 float* __restrict__ out, int B)
{
    extern __shared__ __align__(16) char smem_raw[];
    u64*   SW1 = reinterpret_cast<u64*>(smem_raw);
    u64*   SW2 = SW1 + SW1_N;
    u64*   E1T = SW2 + SW2_N;
    u64*   E2T = E1T + E1T_N;
    u64*   E3S = E2T + E2T_N;
    u64*   W3S = E3S + E3S_N;
    float* IN  = reinterpret_cast<float*>(W3S + W3S_N);
    float* VB  = IN + IN_N;
    float* c1S = VB + VB_N;       // 16
    float* c2S = c1S + 16;        // 16
    float* B1S = c2S + 16;        // 8
    float* B2S = B1S + 8;         // 8

    const int tid  = threadIdx.x;
    const int lane = tid & 31;
    const int warp = tid >> 5;
    const int g    = warp >> 1;   // group 0..3
    const int ws   = warp & 1;    // warp-sub within group
    const int r    = lane >> 1;   // row within group (0..15)
    const int h    = lane & 1;    // output half

    // ---- stage weights / constants ----
    for (int i = tid; i < SW1_N; i += NTHREADS) {
        int fp = i >> 3, o = i & 7;
        SW1[i] = pack2(W1[(2 * fp) * 8 + o], W1[(2 * fp + 1) * 8 + o]);
    }
    for (int i = tid; i < SW2_N; i += NTHREADS) {
        int fp = i >> 3, o = i & 7;
        SW2[i] = pack2(W2[(2 * fp) * 8 + o], W2[(2 * fp + 1) * 8 + o]);
    }
    for (int i = tid; i < E1T_N; i += NTHREADS) {
        int fp = i >> 4, o = i & 15;
        E1T[i] = (fp < 18) ? pack2(E1[(2 * fp) * 16 + o], E1[(2 * fp + 1) * 16 + o])
                           : pack2(E1[36 * 16 + o], 0.0f);
    }
    for (int i = tid; i < E2T_N; i += NTHREADS) {
        int fp = i >> 4, o = i & 15;
        E2T[i] = pack2(E2[(2 * fp) * 16 + o], E2[(2 * fp + 1) * 16 + o]);
    }
    if (tid < 8)  E3S[tid] = pack2(E3[2 * tid], E3[2 * tid + 1]);
    if (tid < 4)  W3S[tid] = pack2(W3[2 * tid], W3[2 * tid + 1]);
    if (tid < 16) { c1S[tid] = c1[tid]; c2S[tid] = c2[tid]; }
    if (tid < 8)  { B1S[tid] = b1[tid]; B2S[tid] = b2[tid]; }

    const float b3s = __ldg(b3);
    const float c3s = __ldg(c3);

    const ulonglong2* SW1v = reinterpret_cast<const ulonglong2*>(SW1);
    const ulonglong2* SW2v = reinterpret_cast<const ulonglong2*>(SW2);
    const ulonglong2* E1Tv = reinterpret_cast<const ulonglong2*>(E1T);
    const ulonglong2* E2Tv = reinterpret_cast<const ulonglong2*>(E2T);

    float* grp_in = IN + g * (ROWS_G * INSTRIDE);
    float* grp_vb = VB + g * (ROWS_G * VSTRIDE);
    float* lane_in = grp_in + r * INSTRIDE;
    float* lane_vb = grp_vb + r * VSTRIDE;

    // head mapping: this warp handles 8 rows
    const int hr  = lane & 7;      // row (within warp's 8)
    const int hoq = lane >> 3;     // output quad
    const float* vrow = grp_vb + (ws * 8 + hr) * VSTRIDE;

    const int rowsPerIter = gridDim.x * ROWS_B;
    const int barid = g + 1;

    __syncthreads();   // weights staged (block-wide, once)

    for (int rb0 = blockIdx.x * ROWS_B; rb0 < B; rb0 += rowsPerIter) {
        const int rbg = rb0 + g * ROWS_G;        // group's first row

        // protect grp_in/grp_vb against previous iteration's head readers
        group_bar(barid);

        // ---- stage: this warp stages 8 rows; unroll 4 -> MLP ~48 ----
#pragma unroll 4
        for (int rr = 0; rr < 8; rr++) {
            const int rloc = ws * 8 + rr;
            const int row  = rbg + rloc;
            float* dst = grp_in + rloc * INSTRIDE;
            if (row < B) {
                const float* src = inp + (size_t)row * 385;
#pragma unroll
                for (int k = 0; k < 12; k++)
                    dst[lane + 32 * k] = __ldg(src + lane + 32 * k);
                if (lane == 0) {
                    grp_vb[rloc * VSTRIDE + 36] = __ldg(src + 384);
                    grp_vb[rloc * VSTRIDE + 37] = 0.0f;
                }
            } else {
#pragma unroll
                for (int k = 0; k < 12; k++)
                    dst[lane + 32 * k] = 0.0f;
                if (lane == 0) {
                    grp_vb[rloc * VSTRIDE + 36] = 0.0f;
                    grp_vb[rloc * VSTRIDE + 37] = 0.0f;
                }
            }
        }
        group_bar(barid);

        // ---- compute: this warp owns x-rows {3*ws, 3*ws+1, 3*ws+2} ----
#pragma unroll 1
        for (int xi = 0; xi < 3; xi++) {
            const int x = 3 * ws + xi;
            const float* base = lane_in + x * 48;

            u64 acc[6][4];
#pragma unroll
            for (int j = 0; j < 6; j++)
#pragma unroll
                for (int q = 0; q < 4; q++) acc[j][q] = 0ull;

            // layer 1: 27 feature-pairs x 6 patches; ox loop NOT unrolled
#pragma unroll 1
            for (int ox = 0; ox < 3; ox++) {
                const float* brow = base + ox * 48;
#pragma unroll
                for (int oy = 0; oy < 3; oy++) {
#pragma unroll
                    for (int j3 = 0; j3 < 3; j3++) {
                        const int fp = 3 * (3 * ox + oy) + j3;
                        const int coff = oy * 6 + 2 * j3;
                        const ulonglong2 wa = SW1v[fp * 4 + 2 * h];
                        const ulonglong2 wb = SW1v[fp * 4 + 2 * h + 1];
#pragma unroll
                        for (int j = 0; j < 6; j++) {
                            const u64 iv = *reinterpret_cast<const u64*>(brow + j * 6 + coff);
                            acc[j][0] = ffma2(iv, wa.x, acc[j][0]);
                            acc[j][1] = ffma2(iv, wa.y, acc[j][1]);
                            acc[j][2] = ffma2(iv, wb.x, acc[j][2]);
                            acc[j][3] = ffma2(iv, wb.y, acc[j][3]);
                        }
                    }
                }
            }

            // epilogue + L2 + L3 per patch (biases/W3 from SMEM broadcast)
            const float b10 = B1S[4 * h], b11 = B1S[4 * h + 1];
            const float b12 = B1S[4 * h + 2], b13 = B1S[4 * h + 3];
            const float b20 = B2S[4 * h], b21 = B2S[4 * h + 1];
            const float b22 = B2S[4 * h + 2], b23 = B2S[4 * h + 3];
            const u64 w3p0 = W3S[2 * h], w3p1 = W3S[2 * h + 1];

#pragma unroll
            for (int j = 0; j < 6; j++) {
                float2 f0 = unpack2(acc[j][0]);
                float2 f1 = unpack2(acc[j][1]);
                float2 f2 = unpack2(acc[j][2]);
                float2 f3 = unpack2(acc[j][3]);
                u64 m0 = pack2(clip1(f0.x + f0.y + b10), clip1(f1.x + f1.y + b11));
                u64 m1 = pack2(clip1(f2.x + f2.y + b12), clip1(f3.x + f3.y + b13));
                u64 p0 = shflx64(m0, 1);
                u64 p1 = shflx64(m1, 1);
                u64 x0 = h ? p0 : m0, x1 = h ? p1 : m1;
                u64 x2 = h ? m0 : p0, x3 = h ? m1 : p1;

                u64 a0 = 0ull, a1 = 0ull, a2 = 0ull, a3 = 0ull;
#pragma unroll
                for (int fp = 0; fp < 4; fp++) {
                    const u64 xv = (fp == 0) ? x0 : (fp == 1) ? x1 : (fp == 2) ? x2 : x3;
                    const ulonglong2 wa2 = SW2v[fp * 4 + 2 * h];
                    const ulonglong2 wb2 = SW2v[fp * 4 + 2 * h + 1];
                    a0 = ffma2(xv, wa2.x, a0);
                    a1 = ffma2(xv, wa2.y, a1);
                    a2 = ffma2(xv, wb2.x, a2);
                    a3 = ffma2(xv, wb2.y, a3);
                }
                float2 g0 = unpack2(a0), g1 = unpack2(a1);
                float2 g2 = unpack2(a2), g3 = unpack2(a3);
                u64 n0 = pack2(clip1(g0.x + g0.y + b20), clip1(g1.x + g1.y + b21));
                u64 n1 = pack2(clip1(g2.x + g2.y + b22), clip1(g3.x + g3.y + b23));

                u64 s = ffma2(n0, w3p0, ffma2(n1, w3p1, 0ull));
                float2 sf = unpack2(s);
                float part = sf.x + sf.y;
                float tot = part + __shfl_xor_sync(0xffffffffu, part, 1);
                if (h == 0) lane_vb[x * 6 + j] = clip1(tot + b3s);
            }
        }
        group_bar(barid);

        // ---- head: this warp handles rows rbg + ws*8 + (0..7) ----
        u64 gacc[4] = {0ull, 0ull, 0ull, 0ull};
#pragma unroll
        for (int fp = 0; fp < 19; fp++) {
            const u64 iv = *reinterpret_cast<const u64*>(vrow + 2 * fp);
            const ulonglong2 wa = E1Tv[fp * 8 + 2 * hoq];
            const ulonglong2 wb = E1Tv[fp * 8 + 2 * hoq + 1];
            gacc[0] = ffma2(iv, wa.x, gacc[0]);
            gacc[1] = ffma2(iv, wa.y, gacc[1]);
            gacc[2] = ffma2(iv, wb.x, gacc[2]);
            gacc[3] = ffma2(iv, wb.y, gacc[3]);
        }
        float gv[4];
#pragma unroll
        for (int k = 0; k < 4; k++) {
            float2 f = unpack2(gacc[k]);
            gv[k] = clip1(f.x + f.y + c1S[4 * hoq + k]);
        }
        u64 q0 = pack2(gv[0], gv[1]), q1 = pack2(gv[2], gv[3]);

        u64 z[8];
#pragma unroll
        for (int c = 0; c < 4; c++) {
            z[2 * c]     = shfl64(q0, c * 8 + hr);
            z[2 * c + 1] = shfl64(q1, c * 8 + hr);
        }

        u64 d[4] = {0ull, 0ull, 0ull, 0ull};
#pragma unroll
        for (int fp = 0; fp < 8; fp++) {
            const ulonglong2 wa = E2Tv[fp * 8 + 2 * hoq];
            const ulonglong2 wb = E2Tv[fp * 8 + 2 * hoq + 1];
            d[0] = ffma2(z[fp], wa.x, d[0]);
            d[1] = ffma2(z[fp], wa.y, d[1]);
            d[2] = ffma2(z[fp], wb.x, d[2]);
            d[3] = ffma2(z[fp], wb.y, d[3]);
        }
        float dv[4];
#pragma unroll
        for (int k = 0; k < 4; k++) {
            float2 f = unpack2(d[k]);
            dv[k] = clip1(f.x + f.y + c2S[4 * hoq + k]);
        }
        u64 s = ffma2(pack2(dv[0], dv[1]), E3S[2 * hoq],
                ffma2(pack2(dv[2], dv[3]), E3S[2 * hoq + 1], 0ull));
        float2 sf = unpack2(s);
        float part = sf.x + sf.y;
        part += __shfl_xor_sync(0xffffffffu, part, 8);
        part += __shfl_xor_sync(0xffffffffu, part, 16);
        const int row = rbg + ws * 8 + hr;
        if (hoq == 0 && row < B) out[row] = clip1(part + c3s);
    }
}

extern "C" void kernel_launch(void* const* d_in, const int* in_sizes, int n_in,
                              void* d_out, int out_size)
{
    const float* inp = (const float*)d_in[0];
    const float* W1  = (const float*)d_in[1];
    const float* b1  = (const float*)d_in[2];
    const float* W2  = (const float*)d_in[3];
    const float* b2  = (const float*)d_in[4];
    const float* W3  = (const float*)d_in[5];
    const float* b3  = (const float*)d_in[6];
    const float* E1  = (const float*)d_in[7];
    const float* c1  = (const float*)d_in[8];
    const float* E2  = (const float*)d_in[9];
    const float* c2  = (const float*)d_in[10];
    const float* E3  = (const float*)d_in[11];
    const float* c3  = (const float*)d_in[12];

    int B = in_sizes[0] / 385;

    cudaFuncSetAttribute(lila_kernel, cudaFuncAttributeMaxDynamicSharedMemorySize,
                         (int)SMEM_BYTES);

    lila_kernel<<<296, NTHREADS, SMEM_BYTES>>>(inp, W1, b1, W2, b2, W3, b3,
                                               E1, c1, E2, c2, E3, c3,
                                               (float*)d_out, B);
}

// round 8
// speedup vs baseline: 2.6700x; 1.0034x over previous
#include <cuda_runtime.h>
#include <cstdint>

typedef unsigned long long u64;
typedef unsigned int u32;

__device__ __forceinline__ u64 ffma2(u64 a, u64 b, u64 c) {
    u64 d; asm("fma.rn.f32x2 %0, %1, %2, %3;" : "=l"(d) : "l"(a), "l"(b), "l"(c)); return d;
}
__device__ __forceinline__ u64 pack2(float x, float y) {
    u64 r; asm("mov.b64 %0, {%1, %2};" : "=l"(r) : "f"(x), "f"(y)); return r;
}
__device__ __forceinline__ float2 unpack2(u64 v) {
    float2 r; asm("mov.b64 {%0, %1}, %2;" : "=f"(r.x), "=f"(r.y) : "l"(v)); return r;
}
__device__ __forceinline__ float clip1(float v) { return fminf(fmaxf(v, -1.0f), 1.0f); }
__device__ __forceinline__ u64 shfl64(u64 v, int src) {
    u32 lo = (u32)v, hi = (u32)(v >> 32);
    lo = __shfl_sync(0xffffffffu, lo, src);
    hi = __shfl_sync(0xffffffffu, hi, src);
    return ((u64)hi << 32) | (u64)lo;
}
__device__ __forceinline__ void group_bar(int id) {
    asm volatile("bar.sync %0, 64;" :: "r"(id) : "memory");
}

constexpr int NTHREADS = 256;
constexpr int NGROUP   = 4;          // 2 warps per group
constexpr int ROWS_G   = 16;         // rows per group
constexpr int ROWS_B   = NGROUP * ROWS_G;   // 64 rows per block-iteration
constexpr int INSTRIDE = 386;        // 386 mod 32 = 2 -> conflict-free across 16 rows
constexpr int VSTRIDE  = 38;

constexpr int SW1_N = 27 * 8;
constexpr int SW2_N = 4 * 8;
constexpr int E1T_N = 19 * 16;
constexpr int E2T_N = 8 * 16;
constexpr int E3S_N = 8;
constexpr int W3S_N = 4;
constexpr int WU_N  = SW1_N + SW2_N + E1T_N + E2T_N + E3S_N + W3S_N;
constexpr int IN_N  = NGROUP * ROWS_G * INSTRIDE;   // floats
constexpr int VB_N  = NGROUP * ROWS_G * VSTRIDE;    // floats
constexpr size_t SMEM_BYTES = (size_t)WU_N * 8 + (size_t)(IN_N + VB_N + 64) * 4;

__global__ __launch_bounds__(NTHREADS, 2)
void lila_kernel(const float* __restrict__ inp,
                 const float* __restrict__ W1, const float* __restrict__ b1,
                 const float* __restrict__ W2, const float* __restrict__ b2,
                 const float* __restrict__ W3, const float* __restrict__ b3,
                 const float* __restrict__ E1, const float* __restrict__ c1,
                 const float* __restrict__ E2, const float* __restrict__ c2,
                 const float* __restrict__ E3, const float* __restrict__ c3,
                 float* __restrict__ out, int B)
{
    extern __shared__ __align__(16) char smem_raw[];
    u64*   SW1 = reinterpret_cast<u64*>(smem_raw);
    u64*   SW2 = SW1 + SW1_N;
    u64*   E1T = SW2 + SW2_N;
    u64*   E2T = E1T + E1T_N;
    u64*   E3S = E2T + E2T_N;
    u64*   W3S = E3S + E3S_N;
    float* IN  = reinterpret_cast<float*>(W3S + W3S_N);
    float* VB  = IN + IN_N;
    float* c1S = VB + VB_N;       // 16
    float* c2S = c1S + 16;        // 16
    float* B1S = c2S + 16;        // 8
    float* B2S = B1S + 8;         // 8

    const int tid  = threadIdx.x;
    const int lane = tid & 31;
    const int warp = tid >> 5;
    const int g    = warp >> 1;   // group 0..3
    const int ws   = warp & 1;    // warp-sub within group
    const int r    = lane >> 1;   // row within group (0..15)
    const int h    = lane & 1;    // patch half: y in {3h..3h+2}

    // ---- stage weights / constants ----
    for (int i = tid; i < SW1_N; i += NTHREADS) {
        int fp = i >> 3, o = i & 7;
        SW1[i] = pack2(W1[(2 * fp) * 8 + o], W1[(2 * fp + 1) * 8 + o]);
    }
    for (int i = tid; i < SW2_N; i += NTHREADS) {
        int fp = i >> 3, o = i & 7;
        SW2[i] = pack2(W2[(2 * fp) * 8 + o], W2[(2 * fp + 1) * 8 + o]);
    }
    for (int i = tid; i < E1T_N; i += NTHREADS) {
        int fp = i >> 4, o = i & 15;
        E1T[i] = (fp < 18) ? pack2(E1[(2 * fp) * 16 + o], E1[(2 * fp + 1) * 16 + o])
                           : pack2(E1[36 * 16 + o], 0.0f);
    }
    for (int i = tid; i < E2T_N; i += NTHREADS) {
        int fp = i >> 4, o = i & 15;
        E2T[i] = pack2(E2[(2 * fp) * 16 + o], E2[(2 * fp + 1) * 16 + o]);
    }
    if (tid < 8)  E3S[tid] = pack2(E3[2 * tid], E3[2 * tid + 1]);
    if (tid < 4)  W3S[tid] = pack2(W3[2 * tid], W3[2 * tid + 1]);
    if (tid < 16) { c1S[tid] = c1[tid]; c2S[tid] = c2[tid]; }
    if (tid < 8)  { B1S[tid] = b1[tid]; B2S[tid] = b2[tid]; }

    const float b3s = __ldg(b3);
    const float c3s = __ldg(c3);

    const ulonglong2* SW1v = reinterpret_cast<const ulonglong2*>(SW1);
    const ulonglong2* SW2v = reinterpret_cast<const ulonglong2*>(SW2);
    const ulonglong2* E1Tv = reinterpret_cast<const ulonglong2*>(E1T);
    const ulonglong2* E2Tv = reinterpret_cast<const ulonglong2*>(E2T);

    float* grp_in = IN + g * (ROWS_G * INSTRIDE);
    float* grp_vb = VB + g * (ROWS_G * VSTRIDE);
    float* lane_in = grp_in + r * INSTRIDE;
    float* lane_vb = grp_vb + r * VSTRIDE;

    // head mapping: this warp handles 8 rows
    const int hr  = lane & 7;      // row (within warp's 8)
    const int hoq = lane >> 3;     // output quad
    const float* vrow = grp_vb + (ws * 8 + hr) * VSTRIDE;

    const int rowsPerIter = gridDim.x * ROWS_B;
    const int barid = g + 1;

    __syncthreads();   // weights staged (block-wide, once)

    for (int rb0 = blockIdx.x * ROWS_B; rb0 < B; rb0 += rowsPerIter) {
        const int rbg = rb0 + g * ROWS_G;        // group's first row

        group_bar(barid);    // protect buffers vs previous iteration readers

        // ---- stage: this warp stages 8 rows; unroll 4 -> high MLP ----
#pragma unroll 4
        for (int rr = 0; rr < 8; rr++) {
            const int rloc = ws * 8 + rr;
            const int row  = rbg + rloc;
            float* dst = grp_in + rloc * INSTRIDE;
            if (row < B) {
                const float* src = inp + (size_t)row * 385;
#pragma unroll
                for (int k = 0; k < 12; k++)
                    dst[lane + 32 * k] = __ldg(src + lane + 32 * k);
                if (lane == 0) {
                    grp_vb[rloc * VSTRIDE + 36] = __ldg(src + 384);
                    grp_vb[rloc * VSTRIDE + 37] = 0.0f;
                }
            } else {
#pragma unroll
                for (int k = 0; k < 12; k++)
                    dst[lane + 32 * k] = 0.0f;
                if (lane == 0) {
                    grp_vb[rloc * VSTRIDE + 36] = 0.0f;
                    grp_vb[rloc * VSTRIDE + 37] = 0.0f;
                }
            }
        }
        group_bar(barid);

        // ---- compute: warp owns x-rows {3*ws..3*ws+2}; lane h owns y {3h..3h+2}
#pragma unroll 1
        for (int xi = 0; xi < 3; xi++) {
            const int x = 3 * ws + xi;

            u64 acc[3][8];
#pragma unroll
            for (int dy = 0; dy < 3; dy++)
#pragma unroll
                for (int o = 0; o < 8; o++) acc[dy][o] = 0ull;

            // layer 1: contiguous 15-u64 cell window per ox
#pragma unroll 1
            for (int ox = 0; ox < 3; ox++) {
                const float* cw = lane_in + (x + ox) * 48 + 18 * h;
                u64 iv[15];
#pragma unroll
                for (int t = 0; t < 15; t++)
                    iv[t] = *reinterpret_cast<const u64*>(cw + 2 * t);

#pragma unroll
                for (int oy = 0; oy < 3; oy++) {
#pragma unroll
                    for (int j3 = 0; j3 < 3; j3++) {
                        const int fp = 9 * ox + 3 * oy + j3;
                        const ulonglong2 wv0 = SW1v[fp * 4 + 0];
                        const ulonglong2 wv1 = SW1v[fp * 4 + 1];
                        const ulonglong2 wv2 = SW1v[fp * 4 + 2];
                        const ulonglong2 wv3 = SW1v[fp * 4 + 3];
#pragma unroll
                        for (int dy = 0; dy < 3; dy++) {
                            const u64 v = iv[(dy + oy) * 3 + j3];
                            acc[dy][0] = ffma2(v, wv0.x, acc[dy][0]);
                            acc[dy][1] = ffma2(v, wv0.y, acc[dy][1]);
                            acc[dy][2] = ffma2(v, wv1.x, acc[dy][2]);
                            acc[dy][3] = ffma2(v, wv1.y, acc[dy][3]);
                            acc[dy][4] = ffma2(v, wv2.x, acc[dy][4]);
                            acc[dy][5] = ffma2(v, wv2.y, acc[dy][5]);
                            acc[dy][6] = ffma2(v, wv3.x, acc[dy][6]);
                            acc[dy][7] = ffma2(v, wv3.y, acc[dy][7]);
                        }
                    }
                }
            }

            // epilogue (fully in-lane; no shuffles)
            float b1r[8], b2r[8];
#pragma unroll
            for (int o = 0; o < 8; o++) { b1r[o] = B1S[o]; b2r[o] = B2S[o]; }
            u64 w3r[4];
#pragma unroll
            for (int q = 0; q < 4; q++) w3r[q] = W3S[q];

#pragma unroll
            for (int dy = 0; dy < 3; dy++) {
                u64 h1p[4];
#pragma unroll
                for (int q = 0; q < 4; q++) {
                    float2 fa = unpack2(acc[dy][2 * q]);
                    float2 fb = unpack2(acc[dy][2 * q + 1]);
                    h1p[q] = pack2(clip1(fa.x + fa.y + b1r[2 * q]),
                                   clip1(fb.x + fb.y + b1r[2 * q + 1]));
                }

                u64 a2[8];
#pragma unroll
                for (int o = 0; o < 8; o++) a2[o] = 0ull;
#pragma unroll
                for (int fp = 0; fp < 4; fp++) {
                    const ulonglong2 wv0 = SW2v[fp * 4 + 0];
                    const ulonglong2 wv1 = SW2v[fp * 4 + 1];
                    const ulonglong2 wv2 = SW2v[fp * 4 + 2];
                    const ulonglong2 wv3 = SW2v[fp * 4 + 3];
                    a2[0] = ffma2(h1p[fp], wv0.x, a2[0]);
                    a2[1] = ffma2(h1p[fp], wv0.y, a2[1]);
                    a2[2] = ffma2(h1p[fp], wv1.x, a2[2]);
                    a2[3] = ffma2(h1p[fp], wv1.y, a2[3]);
                    a2[4] = ffma2(h1p[fp], wv2.x, a2[4]);
                    a2[5] = ffma2(h1p[fp], wv2.y, a2[5]);
                    a2[6] = ffma2(h1p[fp], wv3.x, a2[6]);
                    a2[7] = ffma2(h1p[fp], wv3.y, a2[7]);
                }

                u64 h2p[4];
#pragma unroll
                for (int q = 0; q < 4; q++) {
                    float2 fa = unpack2(a2[2 * q]);
                    float2 fb = unpack2(a2[2 * q + 1]);
                    h2p[q] = pack2(clip1(fa.x + fa.y + b2r[2 * q]),
                                   clip1(fb.x + fb.y + b2r[2 * q + 1]));
                }

                u64 s = ffma2(h2p[0], w3r[0],
                        ffma2(h2p[1], w3r[1],
                        ffma2(h2p[2], w3r[2],
                        ffma2(h2p[3], w3r[3], 0ull))));
                float2 sf = unpack2(s);
                lane_vb[x * 6 + 3 * h + dy] = clip1(sf.x + sf.y + b3s);
            }
        }
        group_bar(barid);

        // ---- head: this warp handles rows rbg + ws*8 + (0..7) ----
        u64 gacc[4] = {0ull, 0ull, 0ull, 0ull};
#pragma unroll
        for (int fp = 0; fp < 19; fp++) {
            const u64 iv = *reinterpret_cast<const u64*>(vrow + 2 * fp);
            const ulonglong2 wa = E1Tv[fp * 8 + 2 * hoq];
            const ulonglong2 wb = E1Tv[fp * 8 + 2 * hoq + 1];
            gacc[0] = ffma2(iv, wa.x, gacc[0]);
            gacc[1] = ffma2(iv, wa.y, gacc[1]);
            gacc[2] = ffma2(iv, wb.x, gacc[2]);
            gacc[3] = ffma2(iv, wb.y, gacc[3]);
        }
        float gv[4];
#pragma unroll
        for (int k = 0; k < 4; k++) {
            float2 f = unpack2(gacc[k]);
            gv[k] = clip1(f.x + f.y + c1S[4 * hoq + k]);
        }
        u64 q0 = pack2(gv[0], gv[1]), q1 = pack2(gv[2], gv[3]);

        u64 z[8];
#pragma unroll
        for (int c = 0; c < 4; c++) {
            z[2 * c]     = shfl64(q0, c * 8 + hr);
            z[2 * c + 1] = shfl64(q1, c * 8 + hr);
        }

        u64 d[4] = {0ull, 0ull, 0ull, 0ull};
#pragma unroll
        for (int fp = 0; fp < 8; fp++) {
            const ulonglong2 wa = E2Tv[fp * 8 + 2 * hoq];
            const ulonglong2 wb = E2Tv[fp * 8 + 2 * hoq + 1];
            d[0] = ffma2(z[fp], wa.x, d[0]);
            d[1] = ffma2(z[fp], wa.y, d[1]);
            d[2] = ffma2(z[fp], wb.x, d[2]);
            d[3] = ffma2(z[fp], wb.y, d[3]);
        }
        float dv[4];
#pragma unroll
        for (int k = 0; k < 4; k++) {
            float2 f = unpack2(d[k]);
            dv[k] = clip1(f.x + f.y + c2S[4 * hoq + k]);
        }
        u64 s = ffma2(pack2(dv[0], dv[1]), E3S[2 * hoq],
                ffma2(pack2(dv[2], dv[3]), E3S[2 * hoq + 1], 0ull));
        float2 sf = unpack2(s);
        float part = sf.x + sf.y;
        part += __shfl_xor_sync(0xffffffffu, part, 8);
        part += __shfl_xor_sync(0xffffffffu, part, 16);
        const int row = rbg + ws * 8 + hr;
        if (hoq == 0 && row < B) out[row] = clip1(part + c3s);
    }
}

extern "C" void kernel_launch(void* const* d_in, const int* in_sizes, int n_in,
                              void* d_out, int out_size)
{
    const float* inp = (const float*)d_in[0];
    const float* W1  = (const float*)d_in[1];
    const float* b1  = (const float*)d_in[2];
    const float* W2  = (const float*)d_in[3];
    const float* b2  = (const float*)d_in[4];
    const float* W3  = (const float*)d_in[5];
    const float* b3  = (const float*)d_in[6];
    const float* E1  = (const float*)d_in[7];
    const float* c1  = (const float*)d_in[8];
    const float* E2  = (const float*)d_in[9];
    const float* c2  = (const float*)d_in[10];
    const float* E3  = (const float*)d_in[11];
    const float* c3  = (const float*)d_in[12];

    int B = in_sizes[0] / 385;

    cudaFuncSetAttribute(lila_kernel, cudaFuncAttributeMaxDynamicSharedMemorySize,
                         (int)SMEM_BYTES);

    lila_kernel<<<296, NTHREADS, SMEM_BYTES>>>(inp, W1, b1, W2, b2, W3, b3,
                                               E1, c1, E2, c2, E3, c3,
                                               (float*)d_out, B);
}